// round 1
// baseline (speedup 1.0000x reference)
#include <cuda_runtime.h>
#include <math.h>

#define B 32
#define T 512
#define U 1024
#define E 1024
#define DIN 256
#define G4 4096        // 4*U
#define KX 1280        // DIN + E
#define KTOT 2304      // KX + U

// ---------------- scratch (device globals: no allocations allowed) ----------
__device__ float g_qpart[16 * B * U];     // 2 MB
__device__ float g_query[B * U];
__device__ float g_logits[B * T];
__device__ float g_attn[B * T];
__device__ float g_context[B * E];
__device__ float g_zpart[8 * B * G4];     // 4 MB

// ---------------- helpers ----------------------------------------------------
__device__ __forceinline__ unsigned long long pack2(float a, float b) {
    unsigned long long r;
    asm("mov.b64 %0, {%1, %2};" : "=l"(r) : "r"(__float_as_uint(a)), "r"(__float_as_uint(b)));
    return r;
}
__device__ __forceinline__ void unpack2(unsigned long long v, float& a, float& b) {
    unsigned int lo, hi;
    asm("mov.b64 {%0, %1}, %2;" : "=r"(lo), "=r"(hi) : "l"(v));
    a = __uint_as_float(lo); b = __uint_as_float(hi);
}
__device__ __forceinline__ unsigned long long fma2(unsigned long long x,
                                                   unsigned long long y,
                                                   unsigned long long a) {
    unsigned long long d;
    asm("fma.rn.f32x2 %0, %1, %2, %3;" : "=l"(d) : "l"(x), "l"(y), "l"(a));
    return d;
}
__device__ __forceinline__ float tanh_hw(float x) {
    float y;
    asm("tanh.approx.f32 %0, %1;" : "=f"(y) : "f"(x));
    return y;
}
__device__ __forceinline__ float sigmoid_acc(float x) {
    return 1.0f / (1.0f + expf(-x));
}

// ---------------- K1: query partial GEMM  (h[32,1024] @ Wa_w[1024,1024]) -----
// grid (U/128=8, 16 k-splits), 128 threads. k-chunk = 64.
__global__ void k1_query_partial(const float* __restrict__ h,
                                 const float* __restrict__ Wa) {
    __shared__ __align__(16) float hs[64 * 34];  // [k][b], stride 34 (even for b64)
    const int tid = threadIdx.x;
    const int u = blockIdx.x * 128 + tid;
    const int kb = blockIdx.y;
    const int k0 = kb * 64;

    for (int idx = tid; idx < 32 * 64; idx += 128) {
        int b = idx >> 6, k = idx & 63;
        hs[k * 34 + b] = h[b * U + k0 + k];
    }
    __syncthreads();

    unsigned long long acc[16];
#pragma unroll
    for (int p = 0; p < 16; p++) acc[p] = 0ull;

#pragma unroll 4
    for (int k = 0; k < 64; k++) {
        float w = Wa[(size_t)(k0 + k) * U + u];
        unsigned long long ww = pack2(w, w);
        const unsigned long long* xp =
            reinterpret_cast<const unsigned long long*>(&hs[k * 34]);
#pragma unroll
        for (int p = 0; p < 16; p++) acc[p] = fma2(xp[p], ww, acc[p]);
    }

    float* outp = g_qpart + (size_t)kb * (B * U);
#pragma unroll
    for (int p = 0; p < 16; p++) {
        float a, b2; unpack2(acc[p], a, b2);
        outp[(2 * p) * U + u] = a;
        outp[(2 * p + 1) * U + u] = b2;
    }
}

// ---------------- K1b: reduce query partials + bias --------------------------
__global__ void k1b_query_reduce(const float* __restrict__ Wa_b) {
    int i = blockIdx.x * 256 + threadIdx.x;
    if (i >= B * U) return;
    float s = Wa_b[i & (U - 1)];
#pragma unroll
    for (int kb = 0; kb < 16; kb++) s += g_qpart[kb * (B * U) + i];
    g_query[i] = s;
}

// ---------------- K2: logits[b,t] = sum_u tanh(q[b,u]+es[b,t,u])*va[u] -------
// grid (B=32, T/16=32), 512 threads (16 warps, one t per warp)
__global__ void k2_scores(const float* __restrict__ es,
                          const float* __restrict__ va_w,
                          const float* __restrict__ va_b) {
    __shared__ float qs[U];
    __shared__ float vs[U];
    const int tid = threadIdx.x;
    const int b = blockIdx.x;
    const int t = blockIdx.y * 16 + (tid >> 5);
    const int lane = tid & 31;

    qs[tid]       = g_query[b * U + tid];
    qs[tid + 512] = g_query[b * U + tid + 512];
    vs[tid]       = va_w[tid];
    vs[tid + 512] = va_w[tid + 512];
    __syncthreads();

    const float* esrow = es + ((size_t)(b * T + t)) * U;
    float s = 0.f;
#pragma unroll 8
    for (int i = 0; i < U / 32; i++) {
        int u = lane + i * 32;
        s += tanh_hw(qs[u] + esrow[u]) * vs[u];
    }
#pragma unroll
    for (int o = 16; o; o >>= 1) s += __shfl_xor_sync(0xffffffffu, s, o);
    if (lane == 0) g_logits[b * T + t] = s + va_b[0];
}

// ---------------- K3: softmax over T per batch -------------------------------
__global__ void k3_softmax() {
    __shared__ float sm[T];
    const int tid = threadIdx.x;
    const int b = blockIdx.x;
    float l = g_logits[b * T + tid];
    sm[tid] = l;
    __syncthreads();
#pragma unroll
    for (int o = 256; o; o >>= 1) {
        if (tid < o) sm[tid] = fmaxf(sm[tid], sm[tid + o]);
        __syncthreads();
    }
    float mx = sm[0];
    __syncthreads();
    float p = __expf(l - mx);
    sm[tid] = p;
    __syncthreads();
#pragma unroll
    for (int o = 256; o; o >>= 1) {
        if (tid < o) sm[tid] += sm[tid + o];
        __syncthreads();
    }
    g_attn[b * T + tid] = p / sm[0];
}

// ---------------- K4: context[b,e] = sum_t attn[b,t]*SE[b,t,e] ---------------
// grid (B=32, E/128=8), 128 threads
__global__ void k4_context(const float* __restrict__ se) {
    __shared__ float as[T];
    const int tid = threadIdx.x;
    const int b = blockIdx.x;
    const int e = blockIdx.y * 128 + tid;

    for (int i = tid; i < T; i += 128) as[i] = g_attn[b * T + i];
    __syncthreads();

    const float* sep = se + (size_t)b * T * E + e;
    float acc = 0.f;
#pragma unroll 8
    for (int t = 0; t < T; t++) acc += as[t] * sep[(size_t)t * E];
    g_context[b * E + e] = acc;
}

// ---------------- K6: z partial GEMM -----------------------------------------
// z[b,j] = sum_k x[b,k]*W[k,j],  K=2304 (inputs 256 | context 1024 | h 1024)
// grid (G4/128=32, 8 k-splits), 128 threads. k-chunk = 288.
__global__ void k6_z_partial(const float* __restrict__ inputs,
                             const float* __restrict__ h,
                             const float* __restrict__ Wk,
                             const float* __restrict__ Wr) {
    __shared__ __align__(16) float xs[288 * 34];  // [k][b] stride 34
    const int tid = threadIdx.x;
    const int j = blockIdx.x * 128 + tid;
    const int kb = blockIdx.y;
    const int k0 = kb * 288;

    for (int b = 0; b < 32; b++) {
        for (int kk = tid; kk < 288; kk += 128) {
            int kg = k0 + kk;
            float v;
            if (kg < DIN)        v = inputs[b * DIN + kg];
            else if (kg < KX)    v = g_context[b * E + (kg - DIN)];
            else                 v = h[b * U + (kg - KX)];
            xs[kk * 34 + b] = v;
        }
    }
    __syncthreads();

    unsigned long long acc[16];
#pragma unroll
    for (int p = 0; p < 16; p++) acc[p] = 0ull;

#pragma unroll 4
    for (int kk = 0; kk < 288; kk++) {
        int kg = k0 + kk;
        const float* wrow = (kg < KX) ? (Wk + (size_t)kg * G4)
                                      : (Wr + (size_t)(kg - KX) * G4);
        float w = wrow[j];
        unsigned long long ww = pack2(w, w);
        const unsigned long long* xp =
            reinterpret_cast<const unsigned long long*>(&xs[kk * 34]);
#pragma unroll
        for (int p = 0; p < 16; p++) acc[p] = fma2(xp[p], ww, acc[p]);
    }

    float* outp = g_zpart + (size_t)kb * (B * G4);
#pragma unroll
    for (int p = 0; p < 16; p++) {
        float a, b2; unpack2(acc[p], a, b2);
        outp[(size_t)(2 * p) * G4 + j] = a;
        outp[(size_t)(2 * p + 1) * G4 + j] = b2;
    }
}

// ---------------- K7: reduce z partials + bias, gates, outputs ---------------
__global__ void k7_gates(const float* __restrict__ c,
                         const float* __restrict__ bias,
                         float* __restrict__ out) {
    int i = blockIdx.x * 256 + threadIdx.x;
    if (i >= B * U) return;
    int b = i >> 10, u = i & (U - 1);

    float z[4];
#pragma unroll
    for (int g = 0; g < 4; g++) {
        int col = g * U + u;
        float s = bias[col];
#pragma unroll
        for (int kb = 0; kb < 8; kb++)
            s += g_zpart[(size_t)kb * (B * G4) + (size_t)b * G4 + col];
        z[g] = s;
    }

    float c_new = sigmoid_acc(z[1]) * c[i] + sigmoid_acc(z[0]) * tanhf(z[2]);
    float h_new = sigmoid_acc(z[3]) * tanhf(c_new);

    out[i]                = h_new;  // lstmout
    out[B * U + i]        = h_new;  // h state
    out[2 * B * U + i]    = c_new;  // c state
}

// ---------------- launcher ----------------------------------------------------
extern "C" void kernel_launch(void* const* d_in, const int* in_sizes, int n_in,
                              void* d_out, int out_size) {
    const float* inputs      = (const float*)d_in[0];
    const float* h           = (const float*)d_in[1];
    const float* c           = (const float*)d_in[2];
    const float* speech_enc  = (const float*)d_in[3];
    const float* encodestate = (const float*)d_in[4];
    const float* Wa_w        = (const float*)d_in[5];
    const float* Wa_b        = (const float*)d_in[6];
    const float* va_w        = (const float*)d_in[7];
    const float* va_b        = (const float*)d_in[8];
    const float* kernel_w    = (const float*)d_in[9];
    const float* rec_kernel  = (const float*)d_in[10];
    const float* bias        = (const float*)d_in[11];
    float* out = (float*)d_out;

    k1_query_partial<<<dim3(U / 128, 16), 128>>>(h, Wa_w);
    k1b_query_reduce<<<(B * U + 255) / 256, 256>>>(Wa_b);
    k2_scores<<<dim3(B, T / 16), 512>>>(encodestate, va_w, va_b);
    k3_softmax<<<B, T>>>();
    k4_context<<<dim3(B, E / 128), 128>>>(speech_enc);
    k6_z_partial<<<dim3(G4 / 128, 8), 128>>>(inputs, h, kernel_w, rec_kernel);
    k7_gates<<<(B * U + 255) / 256, 256>>>(c, bias, out);
}

// round 2
// speedup vs baseline: 1.0392x; 1.0392x over previous
#include <cuda_runtime.h>
#include <math.h>

#define B 32
#define T 512
#define U 1024
#define E 1024
#define DIN 256
#define G4 4096        // 4*U
#define KX 1280        // DIN + E
#define TC 4           // T-split for context
#define TCH (T / TC)   // 128

// ---------------- scratch (device globals: no allocations allowed) ----------
__device__ float g_qpart[16 * B * U];
__device__ float g_query[B * U];
__device__ float g_logits[B * T];
__device__ float g_ctxpart[TC * B * E];
__device__ float g_zpart[8 * B * G4];

// ---------------- helpers ----------------------------------------------------
__device__ __forceinline__ unsigned long long pack2(float a, float b) {
    unsigned long long r;
    asm("mov.b64 %0, {%1, %2};" : "=l"(r) : "r"(__float_as_uint(a)), "r"(__float_as_uint(b)));
    return r;
}
__device__ __forceinline__ void unpack2(unsigned long long v, float& a, float& b) {
    unsigned int lo, hi;
    asm("mov.b64 {%0, %1}, %2;" : "=r"(lo), "=r"(hi) : "l"(v));
    a = __uint_as_float(lo); b = __uint_as_float(hi);
}
__device__ __forceinline__ unsigned long long fma2(unsigned long long x,
                                                   unsigned long long y,
                                                   unsigned long long a) {
    unsigned long long d;
    asm("fma.rn.f32x2 %0, %1, %2, %3;" : "=l"(d) : "l"(x), "l"(y), "l"(a));
    return d;
}
__device__ __forceinline__ float tanh_hw(float x) {
    float y;
    asm("tanh.approx.f32 %0, %1;" : "=f"(y) : "f"(x));
    return y;
}
__device__ __forceinline__ float sigmoid_acc(float x) {
    return 1.0f / (1.0f + expf(-x));
}

// ---------------- K1: query partial GEMM  (h[32,1024] @ Wa_w[1024,1024]) -----
// grid (U/128=8, 16 k-splits), 128 threads. k-chunk = 64.
__global__ void k1_query_partial(const float* __restrict__ h,
                                 const float* __restrict__ Wa) {
    __shared__ __align__(16) float hs[64 * 36];  // [k][b], stride 36 (16B aligned)
    const int tid = threadIdx.x;
    const int u = blockIdx.x * 128 + tid;
    const int kb = blockIdx.y;
    const int k0 = kb * 64;

    for (int idx = tid; idx < 32 * 64; idx += 128) {
        int b = idx >> 6, k = idx & 63;
        hs[k * 36 + b] = h[b * U + k0 + k];
    }
    __syncthreads();

    unsigned long long acc[16];
#pragma unroll
    for (int p = 0; p < 16; p++) acc[p] = 0ull;

#pragma unroll 4
    for (int k = 0; k < 64; k++) {
        float w = Wa[(size_t)(k0 + k) * U + u];
        unsigned long long ww = pack2(w, w);
        const ulonglong2* xp = reinterpret_cast<const ulonglong2*>(&hs[k * 36]);
#pragma unroll
        for (int p = 0; p < 8; p++) {
            ulonglong2 x2 = xp[p];
            acc[2 * p]     = fma2(x2.x, ww, acc[2 * p]);
            acc[2 * p + 1] = fma2(x2.y, ww, acc[2 * p + 1]);
        }
    }

    float* outp = g_qpart + (size_t)kb * (B * U);
#pragma unroll
    for (int p = 0; p < 16; p++) {
        float a, b2; unpack2(acc[p], a, b2);
        outp[(2 * p) * U + u] = a;
        outp[(2 * p + 1) * U + u] = b2;
    }
}

// ---------------- K1b: reduce query partials + bias --------------------------
__global__ void k1b_query_reduce(const float* __restrict__ Wa_b) {
    int i = blockIdx.x * 256 + threadIdx.x;
    if (i >= B * U) return;
    float s = Wa_b[i & (U - 1)];
#pragma unroll
    for (int kb = 0; kb < 16; kb++) s += g_qpart[kb * (B * U) + i];
    g_query[i] = s;
}

// ---------------- K2: logits[b,t] = sum_u tanh(q[b,u]+es[b,t,u])*va[u] -------
// grid (B=32, T/16=32), 512 threads (16 warps, one t per warp). float4 loads.
__global__ void k2_scores(const float* __restrict__ es,
                          const float* __restrict__ va_w,
                          const float* __restrict__ va_b) {
    __shared__ __align__(16) float4 qs[U / 4];
    __shared__ __align__(16) float4 vs[U / 4];
    const int tid = threadIdx.x;
    const int b = blockIdx.x;
    const int t = blockIdx.y * 16 + (tid >> 5);
    const int lane = tid & 31;

    if (tid < 256) qs[tid] = reinterpret_cast<const float4*>(g_query + b * U)[tid];
    else           vs[tid - 256] = reinterpret_cast<const float4*>(va_w)[tid - 256];
    __syncthreads();

    const float4* esrow = reinterpret_cast<const float4*>(es + ((size_t)(b * T + t)) * U);
    float s = 0.f;
#pragma unroll
    for (int i = 0; i < 8; i++) {
        int u4 = lane + i * 32;
        float4 e4 = esrow[u4];
        float4 q4 = qs[u4];
        float4 v4 = vs[u4];
        s += tanh_hw(q4.x + e4.x) * v4.x;
        s += tanh_hw(q4.y + e4.y) * v4.y;
        s += tanh_hw(q4.z + e4.z) * v4.z;
        s += tanh_hw(q4.w + e4.w) * v4.w;
    }
#pragma unroll
    for (int o = 16; o; o >>= 1) s += __shfl_xor_sync(0xffffffffu, s, o);
    if (lane == 0) g_logits[b * T + t] = s + va_b[0];
}

// ---------------- K4: fused softmax + context partial ------------------------
// ctxpart[tc,b,e] = sum_{t in chunk tc} softmax(logits[b,:])[t] * SE[b,t,e]
// grid (B=32, E/512=2, TC=4), 128 threads; each thread owns one float4 column.
__global__ void k4_context(const float* __restrict__ se) {
    __shared__ float ps[T];
    __shared__ float red[128];
    const int tid = threadIdx.x;
    const int b = blockIdx.x;
    const int e4 = blockIdx.y * 128 + tid;   // float4 column index [0,256)
    const int tc = blockIdx.z;

    // full softmax over T (cheap recompute per block)
    float l0 = g_logits[b * T + tid];
    float l1 = g_logits[b * T + tid + 128];
    float l2 = g_logits[b * T + tid + 256];
    float l3 = g_logits[b * T + tid + 384];
    red[tid] = fmaxf(fmaxf(l0, l1), fmaxf(l2, l3));
    __syncthreads();
#pragma unroll
    for (int o = 64; o; o >>= 1) {
        if (tid < o) red[tid] = fmaxf(red[tid], red[tid + o]);
        __syncthreads();
    }
    float mx = red[0];
    __syncthreads();
    float p0 = __expf(l0 - mx), p1 = __expf(l1 - mx);
    float p2 = __expf(l2 - mx), p3 = __expf(l3 - mx);
    ps[tid] = p0; ps[tid + 128] = p1; ps[tid + 256] = p2; ps[tid + 384] = p3;
    red[tid] = p0 + p1 + p2 + p3;
    __syncthreads();
#pragma unroll
    for (int o = 64; o; o >>= 1) {
        if (tid < o) red[tid] += red[tid + o];
        __syncthreads();
    }
    const float inv = 1.0f / red[0];

    const float4* se4 = reinterpret_cast<const float4*>(se) + (size_t)(b * T) * 256;
    float4 acc = make_float4(0.f, 0.f, 0.f, 0.f);
#pragma unroll 8
    for (int t = 0; t < TCH; t++) {
        int tg = tc * TCH + t;
        float p = ps[tg];
        float4 v = se4[(size_t)tg * 256 + e4];
        acc.x += p * v.x; acc.y += p * v.y; acc.z += p * v.z; acc.w += p * v.w;
    }
    acc.x *= inv; acc.y *= inv; acc.z *= inv; acc.w *= inv;
    reinterpret_cast<float4*>(g_ctxpart)[(size_t)(tc * B + b) * 256 + e4] = acc;
}

// ---------------- K6: z partial GEMM -----------------------------------------
// z[b,j] = sum_k x[b,k]*W[k,j],  K=2304 (inputs 256 | context 1024 | h 1024)
// grid (G4/128=32, 8 k-splits), 128 threads. k-chunk = 288.
__global__ void k6_z_partial(const float* __restrict__ inputs,
                             const float* __restrict__ h,
                             const float* __restrict__ Wk,
                             const float* __restrict__ Wr) {
    __shared__ __align__(16) float xs[288 * 36];  // [k][b] stride 36 (16B aligned)
    const int tid = threadIdx.x;
    const int j = blockIdx.x * 128 + tid;
    const int kb = blockIdx.y;
    const int k0 = kb * 288;

    for (int b = 0; b < 32; b++) {
        for (int kk = tid; kk < 288; kk += 128) {
            int kg = k0 + kk;
            float v;
            if (kg < DIN) {
                v = inputs[b * DIN + kg];
            } else if (kg < KX) {
                int e = kg - DIN;
                v = g_ctxpart[(0 * B + b) * E + e] + g_ctxpart[(1 * B + b) * E + e]
                  + g_ctxpart[(2 * B + b) * E + e] + g_ctxpart[(3 * B + b) * E + e];
            } else {
                v = h[b * U + (kg - KX)];
            }
            xs[kk * 36 + b] = v;
        }
    }
    __syncthreads();

    unsigned long long acc[16];
#pragma unroll
    for (int p = 0; p < 16; p++) acc[p] = 0ull;

#pragma unroll 4
    for (int kk = 0; kk < 288; kk++) {
        int kg = k0 + kk;
        const float* wrow = (kg < KX) ? (Wk + (size_t)kg * G4)
                                      : (Wr + (size_t)(kg - KX) * G4);
        float w = wrow[j];
        unsigned long long ww = pack2(w, w);
        const ulonglong2* xp = reinterpret_cast<const ulonglong2*>(&xs[kk * 36]);
#pragma unroll
        for (int p = 0; p < 8; p++) {
            ulonglong2 x2 = xp[p];
            acc[2 * p]     = fma2(x2.x, ww, acc[2 * p]);
            acc[2 * p + 1] = fma2(x2.y, ww, acc[2 * p + 1]);
        }
    }

    float* outp = g_zpart + (size_t)kb * (B * G4);
#pragma unroll
    for (int p = 0; p < 16; p++) {
        float a, b2; unpack2(acc[p], a, b2);
        outp[(size_t)(2 * p) * G4 + j] = a;
        outp[(size_t)(2 * p + 1) * G4 + j] = b2;
    }
}

// ---------------- K7: reduce z partials + bias, gates, outputs ---------------
__global__ void k7_gates(const float* __restrict__ c,
                         const float* __restrict__ bias,
                         float* __restrict__ out) {
    int i = blockIdx.x * 256 + threadIdx.x;
    if (i >= B * U) return;
    int b = i >> 10, u = i & (U - 1);

    float z[4];
#pragma unroll
    for (int g = 0; g < 4; g++) {
        int col = g * U + u;
        float s = bias[col];
#pragma unroll
        for (int kb = 0; kb < 8; kb++)
            s += g_zpart[(size_t)kb * (B * G4) + (size_t)b * G4 + col];
        z[g] = s;
    }

    float c_new = sigmoid_acc(z[1]) * c[i] + sigmoid_acc(z[0]) * tanhf(z[2]);
    float h_new = sigmoid_acc(z[3]) * tanhf(c_new);

    out[i]                = h_new;  // lstmout
    out[B * U + i]        = h_new;  // h state
    out[2 * B * U + i]    = c_new;  // c state
}

// ---------------- launcher ----------------------------------------------------
extern "C" void kernel_launch(void* const* d_in, const int* in_sizes, int n_in,
                              void* d_out, int out_size) {
    const float* inputs      = (const float*)d_in[0];
    const float* h           = (const float*)d_in[1];
    const float* c           = (const float*)d_in[2];
    const float* speech_enc  = (const float*)d_in[3];
    const float* encodestate = (const float*)d_in[4];
    const float* Wa_w        = (const float*)d_in[5];
    const float* Wa_b        = (const float*)d_in[6];
    const float* va_w        = (const float*)d_in[7];
    const float* va_b        = (const float*)d_in[8];
    const float* kernel_w    = (const float*)d_in[9];
    const float* rec_kernel  = (const float*)d_in[10];
    const float* bias        = (const float*)d_in[11];
    float* out = (float*)d_out;

    k1_query_partial<<<dim3(U / 128, 16), 128>>>(h, Wa_w);
    k1b_query_reduce<<<(B * U + 255) / 256, 256>>>(Wa_b);
    k2_scores<<<dim3(B, T / 16), 512>>>(encodestate, va_w, va_b);
    k4_context<<<dim3(B, 2, TC), 128>>>(speech_enc);
    k6_z_partial<<<dim3(G4 / 128, 8), 128>>>(inputs, h, kernel_w, rec_kernel);
    k7_gates<<<(B * U + 255) / 256, 256>>>(c, bias, out);
}

// round 3
// speedup vs baseline: 2.2957x; 2.2091x over previous
#include <cuda_runtime.h>
#include <math.h>

#define B 32
#define T 512
#define U 1024
#define E 1024
#define DIN 256
#define G4 4096        // 4*U
#define KX 1280        // DIN + E
#define TC 16          // T-split for context partials
#define TCH (T / TC)   // 32
#define NSPL 18        // k-splits for z GEMM (10 over kernel, 8 over rec_kernel)
#define KCH 128        // k-chunk

// ---------------- scratch (device globals: no allocations allowed) ----------
__device__ float g_qpart[16 * B * U];
__device__ float g_query[B * U];
__device__ float g_logits[B * T];
__device__ float g_attn[B * T];
__device__ float g_ctxpart[TC * B * E];
__device__ float g_context[B * E];
__device__ float g_zpart[NSPL * B * G4];

// ---------------- helpers ----------------------------------------------------
__device__ __forceinline__ unsigned long long pack2(float a, float b) {
    unsigned long long r;
    asm("mov.b64 %0, {%1, %2};" : "=l"(r) : "r"(__float_as_uint(a)), "r"(__float_as_uint(b)));
    return r;
}
__device__ __forceinline__ void unpack2(unsigned long long v, float& a, float& b) {
    unsigned int lo, hi;
    asm("mov.b64 {%0, %1}, %2;" : "=r"(lo), "=r"(hi) : "l"(v));
    a = __uint_as_float(lo); b = __uint_as_float(hi);
}
__device__ __forceinline__ unsigned long long fma2(unsigned long long x,
                                                   unsigned long long y,
                                                   unsigned long long a) {
    unsigned long long d;
    asm("fma.rn.f32x2 %0, %1, %2, %3;" : "=l"(d) : "l"(x), "l"(y), "l"(a));
    return d;
}
__device__ __forceinline__ float tanh_hw(float x) {
    float y;
    asm("tanh.approx.f32 %0, %1;" : "=f"(y) : "f"(x));
    return y;
}
__device__ __forceinline__ float sigmoid_acc(float x) {
    return 1.0f / (1.0f + expf(-x));
}

// ---------------- K1: query partial GEMM  (h[32,1024] @ Wa_w[1024,1024]) -----
// grid (U/128=8, 16 k-splits), 128 threads. k-chunk = 64.
__global__ void k1_query_partial(const float* __restrict__ h,
                                 const float* __restrict__ Wa) {
    __shared__ __align__(16) float hs[64 * 36];
    const int tid = threadIdx.x;
    const int u = blockIdx.x * 128 + tid;
    const int kb = blockIdx.y;
    const int k0 = kb * 64;

    for (int idx = tid; idx < 32 * 64; idx += 128) {
        int b = idx >> 6, k = idx & 63;
        hs[k * 36 + b] = h[b * U + k0 + k];
    }
    __syncthreads();

    unsigned long long acc[16];
#pragma unroll
    for (int p = 0; p < 16; p++) acc[p] = 0ull;

    const float* wcol = Wa + (size_t)k0 * U + u;
#pragma unroll 8
    for (int k = 0; k < 64; k++) {
        float w = wcol[(size_t)k * U];
        unsigned long long ww = pack2(w, w);
        const ulonglong2* xp = reinterpret_cast<const ulonglong2*>(&hs[k * 36]);
#pragma unroll
        for (int p = 0; p < 8; p++) {
            ulonglong2 x2 = xp[p];
            acc[2 * p]     = fma2(x2.x, ww, acc[2 * p]);
            acc[2 * p + 1] = fma2(x2.y, ww, acc[2 * p + 1]);
        }
    }

    float* outp = g_qpart + (size_t)kb * (B * U);
#pragma unroll
    for (int p = 0; p < 16; p++) {
        float a, b2; unpack2(acc[p], a, b2);
        outp[(2 * p) * U + u] = a;
        outp[(2 * p + 1) * U + u] = b2;
    }
}

// ---------------- K1b: reduce query partials + bias --------------------------
__global__ void k1b_query_reduce(const float* __restrict__ Wa_b) {
    int i = blockIdx.x * 256 + threadIdx.x;
    if (i >= B * U) return;
    float s = Wa_b[i & (U - 1)];
#pragma unroll
    for (int kb = 0; kb < 16; kb++) s += g_qpart[kb * (B * U) + i];
    g_query[i] = s;
}

// ---------------- K2: logits[b,t] = sum_u tanh(q[b,u]+es[b,t,u])*va[u] -------
// grid (B=32, T/16=32), 512 threads (16 warps, one t per warp). float4 loads.
__global__ void k2_scores(const float* __restrict__ es,
                          const float* __restrict__ va_w,
                          const float* __restrict__ va_b) {
    __shared__ __align__(16) float4 qs[U / 4];
    __shared__ __align__(16) float4 vs[U / 4];
    const int tid = threadIdx.x;
    const int b = blockIdx.x;
    const int t = blockIdx.y * 16 + (tid >> 5);
    const int lane = tid & 31;

    if (tid < 256) qs[tid] = reinterpret_cast<const float4*>(g_query + b * U)[tid];
    else           vs[tid - 256] = reinterpret_cast<const float4*>(va_w)[tid - 256];
    __syncthreads();

    const float4* esrow = reinterpret_cast<const float4*>(es + ((size_t)(b * T + t)) * U);
    float4 e[8];
#pragma unroll
    for (int i = 0; i < 8; i++) e[i] = esrow[lane + i * 32];

    float s = 0.f;
#pragma unroll
    for (int i = 0; i < 8; i++) {
        int u4 = lane + i * 32;
        float4 q4 = qs[u4];
        float4 v4 = vs[u4];
        s += tanh_hw(q4.x + e[i].x) * v4.x;
        s += tanh_hw(q4.y + e[i].y) * v4.y;
        s += tanh_hw(q4.z + e[i].z) * v4.z;
        s += tanh_hw(q4.w + e[i].w) * v4.w;
    }
#pragma unroll
    for (int o = 16; o; o >>= 1) s += __shfl_xor_sync(0xffffffffu, s, o);
    if (lane == 0) g_logits[b * T + t] = s + va_b[0];
}

// ---------------- K3: softmax over T per batch (tiny) -------------------------
// grid 32, block 512 (one thread per t)
__global__ void k3_softmax() {
    __shared__ float red[16];
    const int tid = threadIdx.x;
    const int b = blockIdx.x;
    const int lane = tid & 31, wid = tid >> 5;

    float l = g_logits[b * T + tid];
    float m = l;
#pragma unroll
    for (int o = 16; o; o >>= 1) m = fmaxf(m, __shfl_xor_sync(0xffffffffu, m, o));
    if (lane == 0) red[wid] = m;
    __syncthreads();
    if (tid < 32) {
        float v = red[tid & 15];
#pragma unroll
        for (int o = 8; o; o >>= 1) v = fmaxf(v, __shfl_xor_sync(0xffffffffu, v, o));
        if (tid == 0) red[0] = v;
    }
    __syncthreads();
    float mx = red[0];
    float p = __expf(l - mx);
    float sum = p;
#pragma unroll
    for (int o = 16; o; o >>= 1) sum += __shfl_xor_sync(0xffffffffu, sum, o);
    __syncthreads();
    if (lane == 0) red[wid] = sum;
    __syncthreads();
    if (tid < 32) {
        float v = (tid < 16) ? red[tid] : 0.f;
#pragma unroll
        for (int o = 8; o; o >>= 1) v += __shfl_xor_sync(0xffffffffu, v, o);
        if (tid == 0) red[0] = v;
    }
    __syncthreads();
    g_attn[b * T + tid] = p / red[0];
}

// ---------------- K4: context partial (barrier-light, high MLP) ---------------
// ctxpart[tc,b,e] = sum_{t in 32-chunk tc} attn[b,t] * SE[b,t,e]
// grid (B=32, 2, TC=16), 128 threads; each thread one float4 column, 32 loads.
__global__ void k4_context(const float* __restrict__ se) {
    __shared__ float as[TCH];
    const int tid = threadIdx.x;
    const int b = blockIdx.x;
    const int e4 = blockIdx.y * 128 + tid;
    const int tc = blockIdx.z;

    if (tid < TCH) as[tid] = g_attn[b * T + tc * TCH + tid];
    __syncthreads();

    const float4* se4 = reinterpret_cast<const float4*>(se)
                      + ((size_t)(b * T + tc * TCH)) * 256 + e4;
    float4 acc = make_float4(0.f, 0.f, 0.f, 0.f);
#pragma unroll
    for (int t = 0; t < TCH; t++) {
        float p = as[t];
        float4 v = se4[(size_t)t * 256];
        acc.x += p * v.x; acc.y += p * v.y; acc.z += p * v.z; acc.w += p * v.w;
    }
    reinterpret_cast<float4*>(g_ctxpart)[(size_t)(tc * B + b) * 256 + e4] = acc;
}

// ---------------- K5: reduce context partials ---------------------------------
__global__ void k5_ctx_reduce() {
    int i = blockIdx.x * 256 + threadIdx.x;
    if (i >= B * E) return;
    float s = 0.f;
#pragma unroll
    for (int tc = 0; tc < TC; tc++) s += g_ctxpart[tc * (B * E) + i];
    g_context[i] = s;
}

// ---------------- K6: z partial GEMM ------------------------------------------
// z[b,j] = sum_k x[b,k]*W[k,j]. K regions: [0,KX) via Wk (x=inputs|context),
// [KX,KX+U) via Wr (x=h). 18 uniform chunks of 128: 10 in region A, 8 in B.
// grid (G4/256=16, 18), 256 threads.
__global__ void k6_z_partial(const float* __restrict__ inputs,
                             const float* __restrict__ h,
                             const float* __restrict__ Wk,
                             const float* __restrict__ Wr) {
    __shared__ __align__(16) float xs[KCH * 36];
    const int tid = threadIdx.x;
    const int j = blockIdx.x * 256 + tid;
    const int kb = blockIdx.y;
    const bool regA = (kb < 10);
    const int k0 = regA ? kb * KCH : (kb - 10) * KCH;   // offset within region

    // stage x[k][b] for this chunk
    for (int idx = tid; idx < 32 * KCH; idx += 256) {
        int b = idx >> 7;         // idx / 128
        int kk = idx & (KCH - 1); // idx % 128
        int kg = k0 + kk;
        float v;
        if (regA) {
            v = (kg < DIN) ? inputs[b * DIN + kg] : g_context[b * E + (kg - DIN)];
        } else {
            v = h[b * U + kg];
        }
        xs[kk * 36 + b] = v;
    }
    __syncthreads();

    unsigned long long acc[16];
#pragma unroll
    for (int p = 0; p < 16; p++) acc[p] = 0ull;

    const float* wcol = (regA ? Wk : Wr) + (size_t)k0 * G4 + j;
#pragma unroll 8
    for (int kk = 0; kk < KCH; kk++) {
        float w = wcol[(size_t)kk * G4];
        unsigned long long ww = pack2(w, w);
        const ulonglong2* xp = reinterpret_cast<const ulonglong2*>(&xs[kk * 36]);
#pragma unroll
        for (int p = 0; p < 8; p++) {
            ulonglong2 x2 = xp[p];
            acc[2 * p]     = fma2(x2.x, ww, acc[2 * p]);
            acc[2 * p + 1] = fma2(x2.y, ww, acc[2 * p + 1]);
        }
    }

    float* outp = g_zpart + (size_t)kb * (B * G4);
#pragma unroll
    for (int p = 0; p < 16; p++) {
        float a, b2; unpack2(acc[p], a, b2);
        outp[(size_t)(2 * p) * G4 + j] = a;
        outp[(size_t)(2 * p + 1) * G4 + j] = b2;
    }
}

// ---------------- K7: reduce z partials + bias, gates, outputs ----------------
__global__ void k7_gates(const float* __restrict__ c,
                         const float* __restrict__ bias,
                         float* __restrict__ out) {
    int i = blockIdx.x * 128 + threadIdx.x;
    if (i >= B * U) return;
    int b = i >> 10, u = i & (U - 1);

    float z[4];
#pragma unroll
    for (int g = 0; g < 4; g++) {
        int col = g * U + u;
        float s = bias[col];
        const float* zp = g_zpart + (size_t)b * G4 + col;
#pragma unroll
        for (int kb = 0; kb < NSPL; kb++)
            s += zp[(size_t)kb * (B * G4)];
        z[g] = s;
    }

    float c_new = sigmoid_acc(z[1]) * c[i] + sigmoid_acc(z[0]) * tanhf(z[2]);
    float h_new = sigmoid_acc(z[3]) * tanhf(c_new);

    out[i]                = h_new;  // lstmout
    out[B * U + i]        = h_new;  // h state
    out[2 * B * U + i]    = c_new;  // c state
}

// ---------------- launcher ------------------------------------------------------
extern "C" void kernel_launch(void* const* d_in, const int* in_sizes, int n_in,
                              void* d_out, int out_size) {
    const float* inputs      = (const float*)d_in[0];
    const float* h           = (const float*)d_in[1];
    const float* c           = (const float*)d_in[2];
    const float* speech_enc  = (const float*)d_in[3];
    const float* encodestate = (const float*)d_in[4];
    const float* Wa_w        = (const float*)d_in[5];
    const float* Wa_b        = (const float*)d_in[6];
    const float* va_w        = (const float*)d_in[7];
    const float* va_b        = (const float*)d_in[8];
    const float* kernel_w    = (const float*)d_in[9];
    const float* rec_kernel  = (const float*)d_in[10];
    const float* bias        = (const float*)d_in[11];
    float* out = (float*)d_out;

    k1_query_partial<<<dim3(U / 128, 16), 128>>>(h, Wa_w);
    k1b_query_reduce<<<(B * U + 255) / 256, 256>>>(Wa_b);
    k2_scores<<<dim3(B, T / 16), 512>>>(encodestate, va_w, va_b);
    k3_softmax<<<B, T>>>();
    k4_context<<<dim3(B, 2, TC), 128>>>(speech_enc);
    k5_ctx_reduce<<<(B * E + 255) / 256, 256>>>();
    k6_z_partial<<<dim3(G4 / 256, NSPL), 256>>>(inputs, h, kernel_w, rec_kernel);
    k7_gates<<<(B * U + 127) / 128, 128>>>(c, bias, out);
}